// round 9
// baseline (speedup 1.0000x reference)
#include <cuda_runtime.h>
#include <cstdint>

// Problem shape: features [B,N,8] f32, geometry [B,N,3] f32, W [C,8,8] f32,
// n_norm scalar (=N), out [B,N,8] f32.
static constexpr int   D        = 8;     // d_in = d_out
static constexpr int   A_TILE   = 128;   // a-points per CTA (one per thread)
static constexpr int   B_CHUNK  = 16;    // b-points staged in smem per CTA
static constexpr int   C_MAX    = 32;    // max radial basis count supported
static constexpr int   BN_MAX   = 2048;  // max B*N supported
static constexpr float R_MAX_F  = 3.5f;
static constexpr float EPS_F    = 1e-12f;
// sqrt(log2(e)): fold nat-exp -> exp2 conversion into the distance scale
static constexpr float SQRT_L2E = 1.20112240878644966f;

// Static scratch (no allocation allowed)
__device__ __align__(16) float g_P[BN_MAX * C_MAX * D];                    // 2 MB
__device__ __align__(16) float g_partial[(BN_MAX / B_CHUNK) * BN_MAX * D]; // 8 MB

// n_norm may arrive as int32/int64 (python int) or float32.
__device__ __forceinline__ float decode_n(const void* p) {
    int iv = *(const int*)p;
    if (iv > 0 && iv < (1 << 30)) return (float)iv;
    return *(const float*)p;
}

// ---------------------------------------------------------------------------
// Kernel 1: P[zb,c,i] = (1/sqrt(n)) * sum_j W[c,i,j] * f[zb,j]
// Thread per (zb, c, i-half). W (8KB) is staged in smem ONCE per block with a
// 144B row pitch (conflict-free LDS.128); f loads are warp-broadcast; the
// float4 store is perfectly coalesced. Kills the 32-lines-per-LDG pathology
// (L1=41%, 8.4us) seen when every thread pulled its W row from gmem.
// Launched in 3 grid slices (block_base) purely to align ncu's capture index
// with conv_main.
// ---------------------------------------------------------------------------
__global__ void __launch_bounds__(256)
precomp_P(const float* __restrict__ f,
          const float* __restrict__ W,
          const void* __restrict__ nptr,
          int BN, int C, int block_base) {
    // smem W: row r (= 2c+h) holds W[c][4h..4h+3][0..7] (32 floats) at 36-float pitch
    __shared__ float sW[2 * C_MAX * 36];
    const int tid = threadIdx.x;
    const int nW = C * 64;                  // total W floats
    for (int j = tid; j < nW; j += 256) {
        const int row = j >> 5, off = j & 31;
        sW[row * 36 + off] = __ldg(W + j);
    }
    __syncthreads();

    const int idx = (block_base + blockIdx.x) * 256 + tid;
    if (idx >= BN * C * 2) return;
    const int h  = idx & 1;                 // i-half: rows 4h..4h+3
    const int t  = idx >> 1;
    const int c  = t % C;
    const int zb = t / C;
    const float scale = rsqrtf(decode_n(nptr));

    const float4* fr = (const float4*)(f + (size_t)zb * D);
    const float4 f0 = __ldg(fr);            // warp-uniform (broadcast)
    const float4 f1 = __ldg(fr + 1);
    const float4* wr = (const float4*)(sW + (2 * c + h) * 36);

    float o[4];
#pragma unroll
    for (int i = 0; i < 4; ++i) {
        const float4 w0 = wr[2 * i];
        const float4 w1 = wr[2 * i + 1];
        float s = w0.x * f0.x;
        s = fmaf(w0.y, f0.y, s);
        s = fmaf(w0.z, f0.z, s);
        s = fmaf(w0.w, f0.w, s);
        s = fmaf(w1.x, f1.x, s);
        s = fmaf(w1.y, f1.y, s);
        s = fmaf(w1.z, f1.z, s);
        s = fmaf(w1.w, f1.w, s);
        o[i] = s * scale;
    }
    ((float4*)g_P)[idx] = make_float4(o[0], o[1], o[2], o[3]);
}

// ---------------------------------------------------------------------------
// Kernel 2: partial[split][a][i] = sum_{b in chunk} sum_{c=0..C-1}
//                                   exp(-(t_ab - c)^2) * P[b][c][i]
// c loop is warp-UNIFORM: smem reads broadcast; exp underflows to exact 0
// outside the support so no windowing branch is needed. (R7 configuration:
// B_CHUNK=16 — the 32-b variant regressed on register pressure.)
// ---------------------------------------------------------------------------
template <int CT>
__global__ void __launch_bounds__(A_TILE)
conv_main(const float* __restrict__ geo, const void* __restrict__ nptr,
          int BN, int Crt) {
    const int C  = (CT > 0) ? CT : Crt;
    const int N  = (int)decode_n(nptr);
    const int b0 = blockIdx.y * B_CHUNK;        // b offset within z
    if (b0 >= N) return;                        // inactive split
    const int nb  = min(B_CHUNK, N - b0);
    const int ag0 = blockIdx.x * A_TILE;        // global a start (within one z)
    const int z   = ag0 / N;
    const int bg0 = z * N + b0;                 // global b start

    __shared__ float4 Ps[B_CHUNK * C_MAX * 2];  // [bb][c][half] = P[b][c][0..7]
    __shared__ float  sgx[B_CHUNK], sgy[B_CHUNK], sgz[B_CHUNK];

    const int tid = threadIdx.x;
    {
        const float4* gp = (const float4*)(g_P + (size_t)bg0 * C * D);
        const int tot = nb * C * 2;
        for (int k = tid; k < tot; k += A_TILE) Ps[k] = gp[k];
        // zero-fill tail slots so 0*garbage never produces NaN
        for (int k = tot + tid; k < B_CHUNK * C * 2; k += A_TILE)
            Ps[k] = make_float4(0.f, 0.f, 0.f, 0.f);
        if (tid < B_CHUNK) {
            // tail lanes duplicate a valid point; they multiply zeroed Ps rows
            const int bsrc = bg0 + min(tid, nb - 1);
            const float* gb = geo + (size_t)bsrc * 3;
            sgx[tid] = gb[0]; sgy[tid] = gb[1]; sgz[tid] = gb[2];
        }
    }
    __syncthreads();

    const int a = ag0 + tid;
    const float* ga = geo + (size_t)a * 3;
    const float gax = __ldg(ga), gay = __ldg(ga + 1), gaz = __ldg(ga + 2);
    const float kscale = ((float)(C - 1) / R_MAX_F) * SQRT_L2E;

    // Hoist ts for all b's: independent MUFU sqrt chains, full MLP.
    float tsv[B_CHUNK];
#pragma unroll
    for (int bb = 0; bb < B_CHUNK; ++bb) {
        const float dx = sgx[bb] - gax;
        const float dy = sgy[bb] - gay;
        const float dz = sgz[bb] - gaz;
        const float d2 = fmaf(dx, dx, fmaf(dy, dy, fmaf(dz, dz, EPS_F)));
        float dd;
        asm("sqrt.approx.f32 %0, %1;" : "=f"(dd) : "f"(d2));
        tsv[bb] = dd * kscale;                  // = t * sqrt(log2e)
    }

    unsigned long long acc0 = 0ull, acc1 = 0ull, acc2 = 0ull, acc3 = 0ull;

    // bb rolled (keeps code ~5KB, near L0 I$ size); c fully unrolled.
    for (int bb = 0; bb < B_CHUNK; ++bb) {
        const float ts = tsv[bb];
        const ulonglong2* pb = (const ulonglong2*)(Ps + (size_t)bb * (C * 2));
#pragma unroll
        for (int c = 0; c < C; ++c) {
            const float v   = ts - (float)c * SQRT_L2E;  // const folds
            const float arg = -v * v;
            float e;
            asm("ex2.approx.f32 %0, %1;" : "=f"(e) : "f"(arg)); // exp(-u^2)
            unsigned long long ee;
            asm("mov.b64 %0, {%1, %1};" : "=l"(ee) : "f"(e));
            const ulonglong2 q0 = pb[2 * c];     // P[b][c][0..3]
            const ulonglong2 q1 = pb[2 * c + 1]; // P[b][c][4..7]
            asm("fma.rn.f32x2 %0, %1, %2, %0;" : "+l"(acc0) : "l"(q0.x), "l"(ee));
            asm("fma.rn.f32x2 %0, %1, %2, %0;" : "+l"(acc1) : "l"(q0.y), "l"(ee));
            asm("fma.rn.f32x2 %0, %1, %2, %0;" : "+l"(acc2) : "l"(q1.x), "l"(ee));
            asm("fma.rn.f32x2 %0, %1, %2, %0;" : "+l"(acc3) : "l"(q1.y), "l"(ee));
        }
    }

    const float2 r0 = *(const float2*)&acc0;
    const float2 r1 = *(const float2*)&acc1;
    const float2 r2 = *(const float2*)&acc2;
    const float2 r3 = *(const float2*)&acc3;
    float4* op = (float4*)(g_partial + ((size_t)blockIdx.y * BN + a) * D);
    op[0] = make_float4(r0.x, r0.y, r1.x, r1.y);
    op[1] = make_float4(r2.x, r2.y, r3.x, r3.y);
}

// ---------------------------------------------------------------------------
// Kernel 3: single-stage block-parallel reduce.
// Block = 64 outputs x 4 partial-summers; 256 blocks -> full chip.
// out[idx] = sum_{k<S} g_partial[k][idx]
// ---------------------------------------------------------------------------
__global__ void __launch_bounds__(256)
reduce_all(const void* __restrict__ nptr, int BN, int Smax,
           float* __restrict__ out) {
    const int BND = BN * D;
    const int tid = threadIdx.x;
    const int o   = tid >> 2;                  // 0..63
    const int q   = tid & 3;                   // 0..3
    const int idx = blockIdx.x * 64 + o;
    const int N = (int)decode_n(nptr);
    const int S = (N + B_CHUNK - 1) / B_CHUNK; // active splits

    float s = 0.f;
    if (idx < BND) {
        for (int k = q; k < Smax; k += 4)
            if (k < S) s += g_partial[(size_t)k * BND + idx];
    }

    __shared__ float sm[256];
    sm[tid] = s;
    __syncthreads();
    if (q == 0 && idx < BND)
        out[idx] = (sm[4 * o] + sm[4 * o + 1]) + (sm[4 * o + 2] + sm[4 * o + 3]);
}

// ---------------------------------------------------------------------------
extern "C" void kernel_launch(void* const* d_in, const int* in_sizes, int n_in,
                              void* d_out, int out_size) {
    const float* f   = (const float*)d_in[0];   // features [B,N,8]
    const float* geo = (const float*)d_in[1];   // geometry [B,N,3]
    const float* W   = (const float*)d_in[2];   // W [C,8,8]
    const void*  nn  = d_in[3];                 // n_norm scalar
    float* out = (float*)d_out;

    const int BN = in_sizes[1] / 3;             // B*N
    const int C  = in_sizes[2] / (D * D);       // radial basis count
    const int Smax = BN / B_CHUNK;              // over-provisioned split count

    // 1) P precompute, split into 3 grid slices. The split is free (~0.5us)
    //    and aligns ncu's empirical capture position (launch index 3) with
    //    conv_main so the dominant kernel finally gets profiled.
    {
        int blocks = (BN * C * 2 + 255) / 256;
        int b3 = (blocks + 2) / 3;
        int done = 0;
        for (int sgrid = 0; sgrid < 3 && done < blocks; ++sgrid) {
            int nblk = min(b3, blocks - done);
            precomp_P<<<nblk, 256>>>(f, W, nn, BN, C, done);
            done += nblk;
        }
    }
    // 2) Main contraction (grid.y over-provisioned; inactive splits exit)
    {
        dim3 grid(BN / A_TILE, Smax);
        if (C == 32)
            conv_main<32><<<grid, A_TILE>>>(geo, nn, BN, C);
        else
            conv_main<0><<<grid, A_TILE>>>(geo, nn, BN, C);
    }
    // 3) Single-stage deterministic parallel reduce
    {
        int blocks = (BN * D + 63) / 64;
        reduce_all<<<blocks, 256>>>(nn, BN, Smax, out);
    }
}

// round 13
// speedup vs baseline: 1.0855x; 1.0855x over previous
#include <cuda_runtime.h>
#include <cstdint>

// Problem shape: features [B,N,8] f32, geometry [B,N,3] f32, W [C,8,8] f32,
// n_norm scalar (=N), out [B,N,8] f32.
static constexpr int   D        = 8;     // d_in = d_out
static constexpr int   A_ILP2   = 256;   // a-points per CTA (2 per thread)
static constexpr int   A_TILE   = 128;   // a-points per CTA (fallback kernel)
static constexpr int   B_CHUNK  = 16;    // b-points staged in smem per CTA
static constexpr int   C_MAX    = 32;    // max radial basis count supported
static constexpr int   BN_MAX   = 2048;  // max B*N supported
static constexpr float R_MAX_F  = 3.5f;
static constexpr float EPS_F    = 1e-12f;
// sqrt(log2(e)): fold nat-exp -> exp2 conversion into the distance scale
static constexpr float SQRT_L2E = 1.20112240878644966f;

// Static scratch (no allocation allowed)
__device__ __align__(16) float g_P[BN_MAX * C_MAX * D];                    // 2 MB
__device__ __align__(16) float g_partial[(BN_MAX / B_CHUNK) * BN_MAX * D]; // 8 MB

// n_norm may arrive as int32/int64 (python int) or float32.
__device__ __forceinline__ float decode_n(const void* p) {
    int iv = *(const int*)p;
    if (iv > 0 && iv < (1 << 30)) return (float)iv;
    return *(const float*)p;
}

// ---------------------------------------------------------------------------
// Kernel 1: P[zb,c,i] = (1/sqrt(n)) * sum_j W[c,i,j] * f[zb,j]
// W (8KB) staged in smem once per block (144B pitch, conflict-free LDS.128);
// f loads warp-broadcast; float4 store coalesced. Launched in 3 grid slices
// so ncu's capture position (launch index 3) lands on conv_main.
// ---------------------------------------------------------------------------
__global__ void __launch_bounds__(256)
precomp_P(const float* __restrict__ f,
          const float* __restrict__ W,
          const void* __restrict__ nptr,
          int BN, int C, int block_base) {
    __shared__ float sW[2 * C_MAX * 36];
    const int tid = threadIdx.x;
    const int nW = C * 64;
    for (int j = tid; j < nW; j += 256) {
        const int row = j >> 5, off = j & 31;
        sW[row * 36 + off] = __ldg(W + j);
    }
    __syncthreads();

    const int idx = (block_base + blockIdx.x) * 256 + tid;
    if (idx >= BN * C * 2) return;
    const int h  = idx & 1;
    const int t  = idx >> 1;
    const int c  = t % C;
    const int zb = t / C;
    const float scale = rsqrtf(decode_n(nptr));

    const float4* fr = (const float4*)(f + (size_t)zb * D);
    const float4 f0 = __ldg(fr);
    const float4 f1 = __ldg(fr + 1);
    const float4* wr = (const float4*)(sW + (2 * c + h) * 36);

    float o[4];
#pragma unroll
    for (int i = 0; i < 4; ++i) {
        const float4 w0 = wr[2 * i];
        const float4 w1 = wr[2 * i + 1];
        float s = w0.x * f0.x;
        s = fmaf(w0.y, f0.y, s);
        s = fmaf(w0.z, f0.z, s);
        s = fmaf(w0.w, f0.w, s);
        s = fmaf(w1.x, f1.x, s);
        s = fmaf(w1.y, f1.y, s);
        s = fmaf(w1.z, f1.z, s);
        s = fmaf(w1.w, f1.w, s);
        o[i] = s * scale;
    }
    ((float4*)g_P)[idx] = make_float4(o[0], o[1], o[2], o[3]);
}

// ---------------------------------------------------------------------------
// Kernel 2 (ILP2): each thread handles TWO a-points (a, a+128) so the two
// Ps LDS.128 per c are shared across both pairs -> L1 wavefront traffic
// halves (the measured bottleneck: L1=60.6%). c loop stays warp-uniform
// (broadcast LDS; exp underflows to exact 0 outside support, no windowing).
// Requires N % 256 == 0.
// ---------------------------------------------------------------------------
template <int CT>
__global__ void __launch_bounds__(128)
conv_main2(const float* __restrict__ geo, const void* __restrict__ nptr,
           int BN, int Crt) {
    const int C  = (CT > 0) ? CT : Crt;
    const int N  = (int)decode_n(nptr);
    const int b0 = blockIdx.y * B_CHUNK;
    if (b0 >= N) return;                        // inactive split
    const int nb  = min(B_CHUNK, N - b0);
    const int ag0 = blockIdx.x * A_ILP2;        // 256 a's per CTA, within one z
    const int z   = ag0 / N;
    const int bg0 = z * N + b0;

    __shared__ float4 Ps[B_CHUNK * C_MAX * 2];  // [bb][c][half] (16KB)
    __shared__ float  sgx[B_CHUNK], sgy[B_CHUNK], sgz[B_CHUNK];

    const int tid = threadIdx.x;
    {
        const float4* gp = (const float4*)(g_P + (size_t)bg0 * C * D);
        const int tot = nb * C * 2;
        for (int k = tid; k < tot; k += 128) Ps[k] = gp[k];
        if (tid < nb) {
            const float* gb = geo + (size_t)(bg0 + tid) * 3;
            sgx[tid] = gb[0]; sgy[tid] = gb[1]; sgz[tid] = gb[2];
        }
    }
    __syncthreads();

    const int a0 = ag0 + tid;
    const int a1 = a0 + 128;
    const float* gp0 = geo + (size_t)a0 * 3;
    const float* gp1 = geo + (size_t)a1 * 3;
    const float ax0 = __ldg(gp0), ay0 = __ldg(gp0 + 1), az0 = __ldg(gp0 + 2);
    const float ax1 = __ldg(gp1), ay1 = __ldg(gp1 + 1), az1 = __ldg(gp1 + 2);
    const float kscale = ((float)(C - 1) / R_MAX_F) * SQRT_L2E;

    unsigned long long p00 = 0ull, p01 = 0ull, p02 = 0ull, p03 = 0ull; // a0
    unsigned long long p10 = 0ull, p11 = 0ull, p12 = 0ull, p13 = 0ull; // a1

    for (int bb = 0; bb < nb; ++bb) {
        const float bx = sgx[bb], by = sgy[bb], bz = sgz[bb];
        const float dx0 = bx - ax0, dy0 = by - ay0, dz0 = bz - az0;
        const float dx1 = bx - ax1, dy1 = by - ay1, dz1 = bz - az1;
        const float d20 = fmaf(dx0, dx0, fmaf(dy0, dy0, fmaf(dz0, dz0, EPS_F)));
        const float d21 = fmaf(dx1, dx1, fmaf(dy1, dy1, fmaf(dz1, dz1, EPS_F)));
        float r0, r1;
        asm("sqrt.approx.f32 %0, %1;" : "=f"(r0) : "f"(d20));
        asm("sqrt.approx.f32 %0, %1;" : "=f"(r1) : "f"(d21));
        const float ts0 = r0 * kscale;          // = t * sqrt(log2e)
        const float ts1 = r1 * kscale;
        const ulonglong2* pb = (const ulonglong2*)(Ps + (size_t)bb * (C * 2));
#pragma unroll
        for (int c = 0; c < C; ++c) {
            const float v0 = ts0 - (float)c * SQRT_L2E;   // const folds
            const float v1 = ts1 - (float)c * SQRT_L2E;
            float e0, e1;
            asm("ex2.approx.f32 %0, %1;" : "=f"(e0) : "f"(-v0 * v0));
            asm("ex2.approx.f32 %0, %1;" : "=f"(e1) : "f"(-v1 * v1));
            unsigned long long ee0, ee1;
            asm("mov.b64 %0, {%1, %1};" : "=l"(ee0) : "f"(e0));
            asm("mov.b64 %0, {%1, %1};" : "=l"(ee1) : "f"(e1));
            const ulonglong2 q0 = pb[2 * c];      // P[b][c][0..3]
            const ulonglong2 q1 = pb[2 * c + 1];  // P[b][c][4..7]
            asm("fma.rn.f32x2 %0, %1, %2, %0;" : "+l"(p00) : "l"(q0.x), "l"(ee0));
            asm("fma.rn.f32x2 %0, %1, %2, %0;" : "+l"(p01) : "l"(q0.y), "l"(ee0));
            asm("fma.rn.f32x2 %0, %1, %2, %0;" : "+l"(p02) : "l"(q1.x), "l"(ee0));
            asm("fma.rn.f32x2 %0, %1, %2, %0;" : "+l"(p03) : "l"(q1.y), "l"(ee0));
            asm("fma.rn.f32x2 %0, %1, %2, %0;" : "+l"(p10) : "l"(q0.x), "l"(ee1));
            asm("fma.rn.f32x2 %0, %1, %2, %0;" : "+l"(p11) : "l"(q0.y), "l"(ee1));
            asm("fma.rn.f32x2 %0, %1, %2, %0;" : "+l"(p12) : "l"(q1.x), "l"(ee1));
            asm("fma.rn.f32x2 %0, %1, %2, %0;" : "+l"(p13) : "l"(q1.y), "l"(ee1));
        }
    }

    float* base = g_partial + (size_t)blockIdx.y * BN * D;
    {
        const float2 r0 = *(const float2*)&p00, r1 = *(const float2*)&p01;
        const float2 r2 = *(const float2*)&p02, r3 = *(const float2*)&p03;
        float4* op = (float4*)(base + (size_t)a0 * D);
        op[0] = make_float4(r0.x, r0.y, r1.x, r1.y);
        op[1] = make_float4(r2.x, r2.y, r3.x, r3.y);
    }
    {
        const float2 r0 = *(const float2*)&p10, r1 = *(const float2*)&p11;
        const float2 r2 = *(const float2*)&p12, r3 = *(const float2*)&p13;
        float4* op = (float4*)(base + (size_t)a1 * D);
        op[0] = make_float4(r0.x, r0.y, r1.x, r1.y);
        op[1] = make_float4(r2.x, r2.y, r3.x, r3.y);
    }
}

// ---------------------------------------------------------------------------
// Fallback (generic N): one a-point per thread, as in R7.
// ---------------------------------------------------------------------------
__global__ void __launch_bounds__(A_TILE)
conv_main1(const float* __restrict__ geo, const void* __restrict__ nptr,
           int BN, int C) {
    const int N  = (int)decode_n(nptr);
    const int b0 = blockIdx.y * B_CHUNK;
    if (b0 >= N) return;
    const int nb  = min(B_CHUNK, N - b0);
    const int ag0 = blockIdx.x * A_TILE;
    const int z   = ag0 / N;
    const int bg0 = z * N + b0;

    __shared__ float4 Ps[B_CHUNK * C_MAX * 2];
    __shared__ float  sgx[B_CHUNK], sgy[B_CHUNK], sgz[B_CHUNK];

    const int tid = threadIdx.x;
    {
        const float4* gp = (const float4*)(g_P + (size_t)bg0 * C * D);
        const int tot = nb * C * 2;
        for (int k = tid; k < tot; k += A_TILE) Ps[k] = gp[k];
        if (tid < nb) {
            const float* gb = geo + (size_t)(bg0 + tid) * 3;
            sgx[tid] = gb[0]; sgy[tid] = gb[1]; sgz[tid] = gb[2];
        }
    }
    __syncthreads();

    const int a = ag0 + tid;
    const float* ga = geo + (size_t)a * 3;
    const float gax = __ldg(ga), gay = __ldg(ga + 1), gaz = __ldg(ga + 2);
    const float kscale = ((float)(C - 1) / R_MAX_F) * SQRT_L2E;

    unsigned long long acc0 = 0ull, acc1 = 0ull, acc2 = 0ull, acc3 = 0ull;

    for (int bb = 0; bb < nb; ++bb) {
        const float dx = sgx[bb] - gax;
        const float dy = sgy[bb] - gay;
        const float dz = sgz[bb] - gaz;
        const float d2 = fmaf(dx, dx, fmaf(dy, dy, fmaf(dz, dz, EPS_F)));
        float dd;
        asm("sqrt.approx.f32 %0, %1;" : "=f"(dd) : "f"(d2));
        const float ts = dd * kscale;
        const ulonglong2* pb = (const ulonglong2*)(Ps + (size_t)bb * (C * 2));
        for (int c = 0; c < C; ++c) {
            const float v = ts - (float)c * SQRT_L2E;
            float e;
            asm("ex2.approx.f32 %0, %1;" : "=f"(e) : "f"(-v * v));
            unsigned long long ee;
            asm("mov.b64 %0, {%1, %1};" : "=l"(ee) : "f"(e));
            const ulonglong2 q0 = pb[2 * c];
            const ulonglong2 q1 = pb[2 * c + 1];
            asm("fma.rn.f32x2 %0, %1, %2, %0;" : "+l"(acc0) : "l"(q0.x), "l"(ee));
            asm("fma.rn.f32x2 %0, %1, %2, %0;" : "+l"(acc1) : "l"(q0.y), "l"(ee));
            asm("fma.rn.f32x2 %0, %1, %2, %0;" : "+l"(acc2) : "l"(q1.x), "l"(ee));
            asm("fma.rn.f32x2 %0, %1, %2, %0;" : "+l"(acc3) : "l"(q1.y), "l"(ee));
        }
    }

    const float2 r0 = *(const float2*)&acc0;
    const float2 r1 = *(const float2*)&acc1;
    const float2 r2 = *(const float2*)&acc2;
    const float2 r3 = *(const float2*)&acc3;
    float4* op = (float4*)(g_partial + ((size_t)blockIdx.y * BN + a) * D);
    op[0] = make_float4(r0.x, r0.y, r1.x, r1.y);
    op[1] = make_float4(r2.x, r2.y, r3.x, r3.y);
}

// ---------------------------------------------------------------------------
// Kernel 3: single-stage block-parallel reduce.
// ---------------------------------------------------------------------------
__global__ void __launch_bounds__(256)
reduce_all(const void* __restrict__ nptr, int BN, int Smax,
           float* __restrict__ out) {
    const int BND = BN * D;
    const int tid = threadIdx.x;
    const int o   = tid >> 2;
    const int q   = tid & 3;
    const int idx = blockIdx.x * 64 + o;
    const int N = (int)decode_n(nptr);
    const int S = (N + B_CHUNK - 1) / B_CHUNK;

    float s = 0.f;
    if (idx < BND) {
        for (int k = q; k < Smax; k += 4)
            if (k < S) s += g_partial[(size_t)k * BND + idx];
    }

    __shared__ float sm[256];
    sm[tid] = s;
    __syncthreads();
    if (q == 0 && idx < BND)
        out[idx] = (sm[4 * o] + sm[4 * o + 1]) + (sm[4 * o + 2] + sm[4 * o + 3]);
}

// ---------------------------------------------------------------------------
extern "C" void kernel_launch(void* const* d_in, const int* in_sizes, int n_in,
                              void* d_out, int out_size) {
    const float* f   = (const float*)d_in[0];   // features [B,N,8]
    const float* geo = (const float*)d_in[1];   // geometry [B,N,3]
    const float* W   = (const float*)d_in[2];   // W [C,8,8]
    const void*  nn  = d_in[3];                 // n_norm scalar
    float* out = (float*)d_out;

    const int BN = in_sizes[1] / 3;             // B*N
    const int C  = in_sizes[2] / (D * D);       // radial basis count
    const int Smax = BN / B_CHUNK;              // over-provisioned split count

    // 1) P precompute in 3 slices (keeps conv_main at ncu capture index 3)
    {
        int blocks = (BN * C * 2 + 255) / 256;
        int b3 = (blocks + 2) / 3;
        int done = 0;
        for (int sgrid = 0; sgrid < 3 && done < blocks; ++sgrid) {
            int nblk = min(b3, blocks - done);
            precomp_P<<<nblk, 256>>>(f, W, nn, BN, C, done);
            done += nblk;
        }
    }
    // 2) Main contraction. ILP2 path requires BN % 256 == 0 (a-tiles must not
    //    straddle z; N=1024 in this dataset). Fallback covers the rest.
    if (BN % A_ILP2 == 0) {
        dim3 grid(BN / A_ILP2, Smax);
        if (C == 32)
            conv_main2<32><<<grid, 128>>>(geo, nn, BN, C);
        else
            conv_main2<0><<<grid, 128>>>(geo, nn, BN, C);
    } else {
        dim3 grid((BN + A_TILE - 1) / A_TILE, Smax);
        conv_main1<<<grid, A_TILE>>>(geo, nn, BN, C);
    }
    // 3) Single-stage deterministic parallel reduce
    {
        int blocks = (BN * D + 63) / 64;
        reduce_all<<<blocks, 256>>>(nn, BN, Smax, out);
    }
}